// round 13
// baseline (speedup 1.0000x reference)
#include <cuda_runtime.h>
#include <math.h>

// ---------------------------------------------------------------------------
// Sparse UNet block via tap-compacted dense gather-GEMMs.
// GEMM inner loop uses K-pair-folded fma.rn.f32x2: packed {even,odd} K
// partials per (pair,cout), folded by one FADD at epilogue. A read as natural
// LDS.64; W pre-interleaved in gmem once per launch (zero packing movs).
//  - All 70 tap segments compacted in one kernel (ballot atomics); tile plan
//    fused via last-block ticket.
//  - BN batch stats: float4 vectorized, smem-reduced, slot-spread atomics;
//    finalize fused via last-block ticket. Folded into gather as scale/shift.
//  - red.v4 scatter-accumulate (DIRECT store for deconv).
// ---------------------------------------------------------------------------

#define NMAX 200000
#define EPSF 1e-4f
#define GEMM_GRID 1792
#define STATS_GRID 740
#define NSLOT 8

// packed-W arena offsets (u64 elements): {k, cin/2, cout}
#define WT1_OFF 0                      // 27 x 16 x 32  = 13824
#define WTD_OFF 13824                  //  8 x 16 x 64  =  8192
#define WT2_OFF 22016                  // 27 x 32 x 64  = 55296
#define WTU_OFF 77312                  //  8 x 32 x 32  =  8192
#define WT3_OFF 85504                  // 27 x 32 x 32  = 27648
#define WT_TOTAL 113152

__device__ float g_buf[(size_t)NMAX * 64 * 3]; // cat | xc | xc2 (one memset)
__device__ unsigned long long g_wt[WT_TOTAL];
__device__ int2  g_pf[27 * NMAX];
__device__ int2  g_pc[27 * NMAX];
__device__ int2  g_pd[8 * NMAX];
__device__ int2  g_pu[8 * NMAX];
__device__ int   g_cnt[70];            // 0..26 fine | 27..53 coarse | 54..61 down | 62..69 up
__device__ int   g_tb_f[28], g_tb_c[28], g_tb_d[9], g_tb_u[9];
__device__ double g_sums[NSLOT][128];
__device__ float g_scale[64];
__device__ float g_shift[64];
__device__ int   g_stick;
__device__ int   g_ctick;

// ---------------------------------------------------------------------------
__global__ void prep_kernel() {
    int t = threadIdx.x;                       // 1024 threads
    ((double*)g_sums)[t] = 0.0;
    if (t < 70) g_cnt[t] = 0;
    if (t == 0) { g_stick = 0; g_ctick = 0; }
}

// Interleave W along K: g_wt[..][m][j] = {W[2m][j], W[2m+1][j]} per tap.
__global__ void packw_kernel(const float* __restrict__ w1,
                             const float* __restrict__ wd,
                             const float* __restrict__ w2,
                             const float* __restrict__ wu,
                             const float* __restrict__ w3) {
    int i = blockIdx.x * 256 + threadIdx.x;
    if (i >= WT_TOTAL) return;
    const float* src; int base, cin, cout;
    if (i < WTD_OFF)      { src = w1; base = WT1_OFF; cin = 32; cout = 32; }
    else if (i < WT2_OFF) { src = wd; base = WTD_OFF; cin = 32; cout = 64; }
    else if (i < WTU_OFF) { src = w2; base = WT2_OFF; cin = 64; cout = 64; }
    else if (i < WT3_OFF) { src = wu; base = WTU_OFF; cin = 64; cout = 32; }
    else                  { src = w3; base = WT3_OFF; cin = 64; cout = 32; }
    int loc = i - base;
    int per_k = (cin / 2) * cout;
    int k = loc / per_k;
    int rem = loc - k * per_k;
    int m = rem / cout;
    int j = rem - m * cout;
    const float* wk = src + (size_t)k * cin * cout;
    unsigned int lo = __float_as_uint(wk[(2 * m) * cout + j]);
    unsigned int hi = __float_as_uint(wk[(2 * m + 1) * cout + j]);
    g_wt[i] = ((unsigned long long)hi << 32) | lo;
}

// Vectorized per-channel sum & sumsq, finalize fused into last block.
template <int C>
__global__ void stats_kernel(const float* __restrict__ x, int nrows, int ld,
                             const float* __restrict__ gw,
                             const float* __restrict__ bw, float inv_n) {
    constexpr int TPR = C / 4;
    constexpr int RPB = 256 / TPR;
    __shared__ float smS[256 * 4], smQ[256 * 4];
    __shared__ bool lastsm;

    int tid = threadIdx.x;
    int tr = tid % TPR;
    int rg = tid / TPR;
    float4 s = make_float4(0.f, 0.f, 0.f, 0.f);
    float4 q = make_float4(0.f, 0.f, 0.f, 0.f);

    int stride = gridDim.x * RPB;
    #pragma unroll 4
    for (int r = blockIdx.x * RPB + rg; r < nrows; r += stride) {
        float4 v = __ldg((const float4*)(x + (size_t)r * ld) + tr);
        s.x += v.x; s.y += v.y; s.z += v.z; s.w += v.w;
        q.x = fmaf(v.x, v.x, q.x); q.y = fmaf(v.y, v.y, q.y);
        q.z = fmaf(v.z, v.z, q.z); q.w = fmaf(v.w, v.w, q.w);
    }
    ((float4*)smS)[tid] = s;
    ((float4*)smQ)[tid] = q;
    __syncthreads();

    if (rg == 0) {
        #pragma unroll
        for (int j = 1; j < RPB; j++) {
            float4 a = ((float4*)smS)[j * TPR + tr];
            float4 b = ((float4*)smQ)[j * TPR + tr];
            s.x += a.x; s.y += a.y; s.z += a.z; s.w += a.w;
            q.x += b.x; q.y += b.y; q.z += b.z; q.w += b.w;
        }
        int slot = blockIdx.x & (NSLOT - 1);
        int c = tr * 4;
        atomicAdd(&g_sums[slot][c + 0], (double)s.x);
        atomicAdd(&g_sums[slot][c + 1], (double)s.y);
        atomicAdd(&g_sums[slot][c + 2], (double)s.z);
        atomicAdd(&g_sums[slot][c + 3], (double)s.w);
        atomicAdd(&g_sums[slot][64 + c + 0], (double)q.x);
        atomicAdd(&g_sums[slot][64 + c + 1], (double)q.y);
        atomicAdd(&g_sums[slot][64 + c + 2], (double)q.z);
        atomicAdd(&g_sums[slot][64 + c + 3], (double)q.w);
        __threadfence();
    }
    __syncthreads();
    if (tid == 0)
        lastsm = (atomicAdd(&g_stick, 1) == (int)gridDim.x - 1);
    __syncthreads();

    if (lastsm) {
        __threadfence();
        int c = tid;
        if (c < 64) {
            double ss = 0.0, s2 = 0.0;
            #pragma unroll
            for (int j = 0; j < NSLOT; j++) {
                ss += g_sums[j][c];      g_sums[j][c] = 0.0;
                s2 += g_sums[j][64 + c]; g_sums[j][64 + c] = 0.0;
            }
            if (c < C) {
                float mu  = (float)(ss * inv_n);
                float var = (float)(s2 * inv_n) - mu * mu;
                float inv = rsqrtf(var + EPSF);
                float sc  = gw[c] * inv;
                g_scale[c] = sc;
                g_shift[c] = bw[c] - mu * sc;
            }
        }
        if (tid == 0) g_stick = 0;
    }
}

// ---------------------------------------------------------------------------
// One kernel compacts all 70 tap segments; last block computes the tile plan.
// Tile sizes: fine/up -> 128 pairs, coarse/down -> 64 pairs.
__global__ void compact_all_kernel(const int* __restrict__ nf,
                                   const int* __restrict__ nc,
                                   const int* __restrict__ dn,
                                   const int* __restrict__ uci,
                                   const int* __restrict__ uk,
                                   int N, int M) {
    __shared__ bool lastsm;
    int seg = blockIdx.y;
    const int* src = nullptr; int nrows, sent = 0; int2* out; bool dec = false; int kd = 0;
    if (seg < 27)      { src = nf + (size_t)seg * N;        nrows = N; sent = N; out = g_pf + (size_t)seg * NMAX; }
    else if (seg < 54) { src = nc + (size_t)(seg - 27) * M; nrows = M; sent = M; out = g_pc + (size_t)(seg - 27) * NMAX; }
    else if (seg < 62) { src = dn + (size_t)(seg - 54) * M; nrows = M; sent = N; out = g_pd + (size_t)(seg - 54) * NMAX; }
    else               { nrows = N; out = g_pu + (size_t)(seg - 62) * NMAX; dec = true; kd = seg - 62; }
    int* cnt = &g_cnt[seg];
    int lane = threadIdx.x & 31;
    int base = (blockIdx.x * 256 + threadIdx.x) * 4;

    #pragma unroll
    for (int j = 0; j < 4; j++) {
        int r = base + j;
        int idx = 0; bool valid = false;
        if (r < nrows) {
            if (dec) { valid = (__ldg(uk + r) == kd); idx = __ldg(uci + r); }
            else     { idx = __ldg(src + r); valid = idx < sent; }
        }
        unsigned m = __ballot_sync(0xffffffffu, valid);
        if (m) {
            int ldr = __ffs(m) - 1;
            int pos = 0;
            if (lane == ldr) pos = atomicAdd(cnt, __popc(m));
            pos = __shfl_sync(0xffffffffu, pos, ldr);
            if (valid) out[pos + __popc(m & ((1u << lane) - 1))] = make_int2(r, idx);
        }
    }

    __threadfence();
    __syncthreads();
    if (threadIdx.x == 0) {
        int total = (int)(gridDim.x * gridDim.y);
        lastsm = (atomicAdd(&g_ctick, 1) == total - 1);
    }
    __syncthreads();

    if (lastsm) {
        __threadfence();
        int t = threadIdx.x;
        if (t < 4) {
            const int off0[5] = {0, 27, 54, 62, 70};
            const int tp[4]   = {128, 64, 64, 128};   // fine, coarse, down, up
            int* tb = (t == 0) ? g_tb_f : (t == 1) ? g_tb_c : (t == 2) ? g_tb_d : g_tb_u;
            int s = 0;
            for (int k = off0[t]; k < off0[t + 1]; k++) {
                tb[k - off0[t]] = s;
                s += (g_cnt[k] + tp[t] - 1) / tp[t];
            }
            tb[off0[t + 1] - off0[t]] = s;
        }
        if (threadIdx.x == 0) g_ctick = 0;
    }
}

// ---------------------------------------------------------------------------
__device__ __forceinline__ void red_add_v4(float* a, float x, float y, float z, float w) {
    asm volatile("red.global.add.v4.f32 [%0], {%1,%2,%3,%4};"
                 :: "l"(a), "f"(x), "f"(y), "f"(z), "f"(w) : "memory");
}
__device__ __forceinline__ void fma2(unsigned long long& d,
                                     unsigned long long a, unsigned long long b) {
    asm("fma.rn.f32x2 %0, %1, %2, %0;" : "+l"(d) : "l"(a), "l"(b));
}
union U2F { unsigned long long u; float2 f; };

// Tap-segmented gather-GEMM with K-pair-folded f32x2.
// 256 threads, TP pairs/tile, TX cout groups (CT=COUT/TX=4 couts/thread),
// 4 pairs per thread. Per 2 K-channels: 4 A-LDS.64 + 2 W-LDS.128 + 16 FFMA2.
// acc[pair][cout] holds {even-K, odd-K} partials; folded at epilogue.
template <int CIN, int COUT, int TP, int TX, bool DIRECT>
__launch_bounds__(256)
__global__ void tapgemm_kernel(const float* __restrict__ fin, int ld_in,
                               const int2* __restrict__ pairs,
                               const int* __restrict__ cnt,
                               const int* __restrict__ tb, int K,
                               const unsigned long long* __restrict__ Wt,
                               float* __restrict__ out, int ld_out) {
    constexpr int CP = CIN + 2;     // padded A stride (even -> 8B-aligned rows)
    constexpr int CT = COUT / TX;   // couts per thread (=4)
    constexpr int C4 = CIN / 4;
    constexpr int MH = CIN / 2;     // K-pairs

    __shared__ __align__(16) unsigned long long Wsm2[MH * COUT];
    __shared__ __align__(16) float Asm[TP * CP];
    __shared__ int   rowsm[TP];
    __shared__ int   idxsm[TP];
    __shared__ float ssm[64], bsm[64];
    __shared__ int   tbsm[32], cntsm[32];

    int tid = threadIdx.x;
    if (tid < CIN) { ssm[tid] = g_scale[tid]; bsm[tid] = g_shift[tid]; }
    if (tid <= K)  tbsm[tid] = tb[tid];
    if (tid <  K)  cntsm[tid] = cnt[tid];
    __syncthreads();

    int total = tbsm[K];
    int tx = tid % TX;       // cout group
    int ty = tid / TX;       // pair group
    int pa = ty * 4;

    for (int t = blockIdx.x; t < total; t += gridDim.x) {
        int k = 0;
        while (tbsm[k + 1] <= t) k++;
        int t0 = (t - tbsm[k]) * TP;
        int np = min(TP, cntsm[k] - t0);

        // stage packed W tap + pair chunk
        {
            const ulonglong2* Wg =
                (const ulonglong2*)(Wt + (size_t)k * MH * COUT);
            for (int i = tid; i < MH * COUT / 2; i += 256)
                ((ulonglong2*)Wsm2)[i] = __ldg(&Wg[i]);
            if (tid < TP) {
                if (tid < np) {
                    int2 pr = __ldg(&pairs[(size_t)k * NMAX + t0 + tid]);
                    rowsm[tid] = pr.x; idxsm[tid] = pr.y;
                } else { rowsm[tid] = -1; idxsm[tid] = 0; }
            }
        }
        __syncthreads();

        // gather + BN + ReLU into padded Asm
        for (int i = tid; i < TP * C4; i += 256) {
            int p  = i / C4;
            int c4 = i % C4;
            float4 v = __ldg((const float4*)(fin + (size_t)idxsm[p] * ld_in) + c4);
            int c = c4 * 4;
            float* ap = &Asm[p * CP + c];
            ap[0] = fmaxf(fmaf(v.x, ssm[c + 0], bsm[c + 0]), 0.f);
            ap[1] = fmaxf(fmaf(v.y, ssm[c + 1], bsm[c + 1]), 0.f);
            ap[2] = fmaxf(fmaf(v.z, ssm[c + 2], bsm[c + 2]), 0.f);
            ap[3] = fmaxf(fmaf(v.w, ssm[c + 3], bsm[c + 3]), 0.f);
        }
        __syncthreads();

        // K-pair-folded register GEMM
        unsigned long long acc[4][CT];
        #pragma unroll
        for (int i = 0; i < 4; i++)
            #pragma unroll
            for (int j = 0; j < CT; j++) acc[i][j] = 0ull;

        const float* a0p = &Asm[pa * CP];
        #pragma unroll 4
        for (int m = 0; m < MH; m++) {
            unsigned long long a0 = *(const unsigned long long*)(a0p + 2 * m);
            unsigned long long a1 = *(const unsigned long long*)(a0p + CP + 2 * m);
            unsigned long long a2 = *(const unsigned long long*)(a0p + 2 * CP + 2 * m);
            unsigned long long a3 = *(const unsigned long long*)(a0p + 3 * CP + 2 * m);
            const ulonglong2* wp = (const ulonglong2*)(Wsm2 + m * COUT + tx * CT);
            ulonglong2 wA = wp[0];
            ulonglong2 wB = wp[1];
            fma2(acc[0][0], a0, wA.x); fma2(acc[0][1], a0, wA.y);
            fma2(acc[0][2], a0, wB.x); fma2(acc[0][3], a0, wB.y);
            fma2(acc[1][0], a1, wA.x); fma2(acc[1][1], a1, wA.y);
            fma2(acc[1][2], a1, wB.x); fma2(acc[1][3], a1, wB.y);
            fma2(acc[2][0], a2, wA.x); fma2(acc[2][1], a2, wA.y);
            fma2(acc[2][2], a2, wB.x); fma2(acc[2][3], a2, wB.y);
            fma2(acc[3][0], a3, wA.x); fma2(acc[3][1], a3, wA.y);
            fma2(acc[3][2], a3, wB.x); fma2(acc[3][3], a3, wB.y);
        }

        // fold even/odd partials and write back
        #pragma unroll
        for (int i = 0; i < 4; i++) {
            int r = rowsm[pa + i];
            if (r >= 0) {
                U2F u0, u1, u2, u3;
                u0.u = acc[i][0]; u1.u = acc[i][1];
                u2.u = acc[i][2]; u3.u = acc[i][3];
                float x = u0.f.x + u0.f.y;
                float y = u1.f.x + u1.f.y;
                float z = u2.f.x + u2.f.y;
                float w = u3.f.x + u3.f.y;
                float* op = out + (size_t)r * ld_out + tx * CT;
                if (DIRECT) *(float4*)op = make_float4(x, y, z, w);
                else        red_add_v4(op, x, y, z, w);
            }
        }
        __syncthreads();
    }
}

// ---------------------------------------------------------------------------
extern "C" void kernel_launch(void* const* d_in, const int* in_sizes, int n_in,
                              void* d_out, int out_size) {
    const float* feat    = (const float*)d_in[0];
    const float* w_sub1  = (const float*)d_in[1];
    const float* w_down  = (const float*)d_in[2];
    const float* w_sub2  = (const float*)d_in[3];
    const float* w_up    = (const float*)d_in[4];
    const float* w_sub3  = (const float*)d_in[5];
    const float* g1 = (const float*)d_in[6];  const float* b1 = (const float*)d_in[7];
    const float* g2 = (const float*)d_in[8];  const float* b2 = (const float*)d_in[9];
    const float* g3 = (const float*)d_in[10]; const float* b3 = (const float*)d_in[11];
    const float* g4 = (const float*)d_in[12]; const float* b4 = (const float*)d_in[13];
    const float* g5 = (const float*)d_in[14]; const float* b5 = (const float*)d_in[15];
    const int* nbr_fine   = (const int*)d_in[16];
    const int* nbr_coarse = (const int*)d_in[17];
    const int* down_idx   = (const int*)d_in[18];
    const int* up_cidx    = (const int*)d_in[19];
    const int* up_k       = (const int*)d_in[20];

    const int N = in_sizes[0] / 32;
    const int M = in_sizes[18] / 8;

    float* buf;
    unsigned long long* wt;
    int *cnt_ptr, *tbf, *tbc, *tbd, *tbu;
    cudaGetSymbolAddress((void**)&buf, g_buf);
    cudaGetSymbolAddress((void**)&wt, g_wt);
    cudaGetSymbolAddress((void**)&cnt_ptr, g_cnt);
    cudaGetSymbolAddress((void**)&tbf, g_tb_f);
    cudaGetSymbolAddress((void**)&tbc, g_tb_c);
    cudaGetSymbolAddress((void**)&tbd, g_tb_d);
    cudaGetSymbolAddress((void**)&tbu, g_tb_u);
    int2 *pf, *pc, *pd, *pu;
    cudaGetSymbolAddress((void**)&pf, g_pf);
    cudaGetSymbolAddress((void**)&pc, g_pc);
    cudaGetSymbolAddress((void**)&pd, g_pd);
    cudaGetSymbolAddress((void**)&pu, g_pu);

    float* cat_ptr = buf;
    float* xc_ptr  = buf + (size_t)NMAX * 64;
    float* xc2_ptr = buf + (size_t)NMAX * 64 * 2;

    // zero accumulation targets (cat/xc/xc2 contiguous -> one memset)
    cudaMemsetAsync(buf, 0, ((size_t)N * 64 +
                             (size_t)(NMAX + M) * 64) * sizeof(float));
    cudaMemsetAsync(d_out, 0, (size_t)out_size * sizeof(float));

    // geometry + weight prep (feature-independent)
    prep_kernel<<<1, 1024>>>();
    packw_kernel<<<(WT_TOTAL + 255) / 256, 256>>>(w_sub1, w_down, w_sub2, w_up, w_sub3);
    int mx = (N > M ? N : M);
    dim3 cg((mx + 1023) / 1024, 70);
    compact_all_kernel<<<cg, 256>>>(nbr_fine, nbr_coarse, down_idx, up_cidx, up_k, N, M);

    // stage 1: BN(feat) -> subconv1 (32->32, fine taps) into cat[:,0:32]
    stats_kernel<32><<<STATS_GRID, 256>>>(feat, N, 32, g1, b1, 1.0f / N);
    tapgemm_kernel<32, 32, 128, 8, false><<<GEMM_GRID, 256>>>(
        feat, 32, pf, cnt_ptr + 0, tbf, 27, wt + WT1_OFF, cat_ptr, 64);

    // stage 2: BN(skip) -> down conv (32->64) into xc
    stats_kernel<32><<<STATS_GRID, 256>>>(cat_ptr, N, 64, g2, b2, 1.0f / N);
    tapgemm_kernel<32, 64, 64, 16, false><<<GEMM_GRID, 256>>>(
        cat_ptr, 64, pd, cnt_ptr + 54, tbd, 8, wt + WTD_OFF, xc_ptr, 64);

    // stage 3: BN(xc) -> subconv2 (64->64, coarse taps) into xc2
    stats_kernel<64><<<STATS_GRID, 256>>>(xc_ptr, M, 64, g3, b3, 1.0f / M);
    tapgemm_kernel<64, 64, 64, 16, false><<<GEMM_GRID, 256>>>(
        xc_ptr, 64, pc, cnt_ptr + 27, tbc, 27, wt + WT2_OFF, xc2_ptr, 64);

    // stage 4: BN(xc2) -> deconv (64->32) direct into cat[:,32:64]
    stats_kernel<64><<<STATS_GRID, 256>>>(xc2_ptr, M, 64, g4, b4, 1.0f / M);
    tapgemm_kernel<64, 32, 128, 8, true><<<GEMM_GRID, 256>>>(
        xc2_ptr, 64, pu, cnt_ptr + 62, tbu, 8, wt + WTU_OFF, cat_ptr + 32, 64);

    // stage 5: BN(cat) -> subconv3 (64->32, fine taps) into out
    stats_kernel<64><<<STATS_GRID, 256>>>(cat_ptr, N, 64, g5, b5, 1.0f / N);
    tapgemm_kernel<64, 32, 128, 8, false><<<GEMM_GRID, 256>>>(
        cat_ptr, 64, pf, cnt_ptr + 0, tbf, 27, wt + WT3_OFF, (float*)d_out, 32);
}

// round 15
// speedup vs baseline: 1.2549x; 1.2549x over previous
#include <cuda_runtime.h>
#include <math.h>

// ---------------------------------------------------------------------------
// Sparse UNet block via tap-compacted dense gather-GEMMs (f32x2-packed FFMA).
//  - All 70 tap segments compacted in one kernel (ballot atomics, 8 elem/thr);
//    tile plan fused via last-block ticket.
//  - Each stage = ONE fused launch: persistent 592-block grid does BN stats
//    (float4, smem-reduced, slot-spread atomics), last block finalizes
//    scale/shift + bumps a generation counter, all blocks spin (tid0 +
//    nanosleep, co-residency guaranteed by __launch_bounds__(256,4)), then run
//    the tap-GEMM phase (R8 geometry: thread tile 4 pairs x 4 couts, W in
//    smem float4, fma.rn.f32x2 over cout pairs, red.v4 scatter / DIRECT).
// ---------------------------------------------------------------------------

#define NMAX 200000
#define EPSF 1e-4f
#define STAGE_GRID 592
#define NSLOT 8

__device__ float g_buf[(size_t)NMAX * 64 * 3]; // cat | xc | xc2 (one memset)
__device__ int2  g_pf[27 * NMAX];
__device__ int2  g_pc[27 * NMAX];
__device__ int2  g_pd[8 * NMAX];
__device__ int2  g_pu[8 * NMAX];
__device__ int   g_cnt[70];            // 0..26 fine | 27..53 coarse | 54..61 down | 62..69 up
__device__ int   g_tb_f[28], g_tb_c[28], g_tb_d[9], g_tb_u[9];
__device__ double g_sums[NSLOT][128];
__device__ float g_scale[64];
__device__ float g_shift[64];
__device__ int   g_stick;              // stats ticket (per stage)
__device__ int   g_ctick;              // compact ticket
__device__ int   g_gen;                // stats generation counter (monotonic)

// ---------------------------------------------------------------------------
__global__ void prep_kernel() {
    int t = threadIdx.x;                       // 1024 threads
    ((double*)g_sums)[t] = 0.0;
    if (t < 70) g_cnt[t] = 0;
    if (t == 0) { g_stick = 0; g_ctick = 0; }
}

// ---------------------------------------------------------------------------
// One kernel compacts all 70 tap segments (8 elems/thread); last block
// computes the tile-plan prefix sums. Tile sizes: fine/up 128, coarse/down 64.
__global__ void compact_all_kernel(const int* __restrict__ nf,
                                   const int* __restrict__ nc,
                                   const int* __restrict__ dn,
                                   const int* __restrict__ uci,
                                   const int* __restrict__ uk,
                                   int N, int M) {
    __shared__ bool lastsm;
    int seg = blockIdx.y;
    const int* src = nullptr; int nrows, sent = 0; int2* out; bool dec = false; int kd = 0;
    if (seg < 27)      { src = nf + (size_t)seg * N;        nrows = N; sent = N; out = g_pf + (size_t)seg * NMAX; }
    else if (seg < 54) { src = nc + (size_t)(seg - 27) * M; nrows = M; sent = M; out = g_pc + (size_t)(seg - 27) * NMAX; }
    else if (seg < 62) { src = dn + (size_t)(seg - 54) * M; nrows = M; sent = N; out = g_pd + (size_t)(seg - 54) * NMAX; }
    else               { nrows = N; out = g_pu + (size_t)(seg - 62) * NMAX; dec = true; kd = seg - 62; }
    int* cnt = &g_cnt[seg];
    int lane = threadIdx.x & 31;
    int base = (blockIdx.x * 256 + threadIdx.x) * 8;

    #pragma unroll
    for (int j = 0; j < 8; j++) {
        int r = base + j;
        int idx = 0; bool valid = false;
        if (r < nrows) {
            if (dec) { valid = (__ldg(uk + r) == kd); idx = __ldg(uci + r); }
            else     { idx = __ldg(src + r); valid = idx < sent; }
        }
        unsigned m = __ballot_sync(0xffffffffu, valid);
        if (m) {
            int ldr = __ffs(m) - 1;
            int pos = 0;
            if (lane == ldr) pos = atomicAdd(cnt, __popc(m));
            pos = __shfl_sync(0xffffffffu, pos, ldr);
            if (valid) out[pos + __popc(m & ((1u << lane) - 1))] = make_int2(r, idx);
        }
    }

    __threadfence();
    __syncthreads();
    if (threadIdx.x == 0) {
        int total = (int)(gridDim.x * gridDim.y);
        lastsm = (atomicAdd(&g_ctick, 1) == total - 1);
    }
    __syncthreads();

    if (lastsm) {
        __threadfence();
        int t = threadIdx.x;
        if (t < 4) {
            const int off0[5] = {0, 27, 54, 62, 70};
            const int tp[4]   = {128, 64, 64, 128};   // fine, coarse, down, up
            int* tb = (t == 0) ? g_tb_f : (t == 1) ? g_tb_c : (t == 2) ? g_tb_d : g_tb_u;
            int s = 0;
            for (int k = off0[t]; k < off0[t + 1]; k++) {
                tb[k - off0[t]] = s;
                s += (g_cnt[k] + tp[t] - 1) / tp[t];
            }
            tb[off0[t + 1] - off0[t]] = s;
        }
        if (threadIdx.x == 0) g_ctick = 0;
    }
}

// ---------------------------------------------------------------------------
__device__ __forceinline__ void red_add_v4(float* a, float x, float y, float z, float w) {
    asm volatile("red.global.add.v4.f32 [%0], {%1,%2,%3,%4};"
                 :: "l"(a), "f"(x), "f"(y), "f"(z), "f"(w) : "memory");
}
__device__ __forceinline__ unsigned long long pack2(float a) {
    unsigned long long r;
    asm("mov.b64 %0, {%1, %1};" : "=l"(r) : "r"(__float_as_uint(a)));
    return r;
}
__device__ __forceinline__ void fma2(unsigned long long& d,
                                     unsigned long long a, unsigned long long b) {
    asm("fma.rn.f32x2 %0, %1, %2, %0;" : "+l"(d) : "l"(a), "l"(b));
}
union U2F { unsigned long long u; float2 f; };

// ---------------------------------------------------------------------------
// Fused stage: BN stats over xin (CIN channels, stride ld_in) -> grid-wide
// handoff via ticket + generation spin -> tap-GEMM phase (R8 core).
// TP pairs/tile, TX cout groups (CT = COUT/TX = 4), 4 pairs per thread.
template <int CIN, int COUT, int TP, int TX, bool DIRECT>
__global__ __launch_bounds__(256, 4)
void stage_kernel(const float* __restrict__ xin, int ld_in, int nrows,
                  const float* __restrict__ gw, const float* __restrict__ bw,
                  float inv_n,
                  const int2* __restrict__ pairs,
                  const int* __restrict__ cnt,
                  const int* __restrict__ tb, int K,
                  const float* __restrict__ W,
                  float* __restrict__ out, int ld_out) {
    constexpr int CP = CIN + 2;
    constexpr int CT = COUT / TX;   // = 4
    constexpr int CU = CT / 2;      // = 2
    constexpr int C4 = CIN / 4;

    __shared__ __align__(16) float Wsm[CIN * COUT];
    __shared__ __align__(16) float Asm[TP * CP];
    __shared__ int   rowsm[128];
    __shared__ int   idxsm[128];
    __shared__ float ssm[64], bsm[64];
    __shared__ int   tbsm[32], cntsm[32];
    __shared__ bool  lastsm;

    int tid = threadIdx.x;

    // ---------------- phase A: BN batch stats over xin ----------------
    {
        constexpr int TPR = CIN / 4;
        constexpr int RPB = 256 / TPR;
        float* smS = Asm;            // alias: 1024 floats
        float* smQ = Asm + 1024;     // alias: 1024 floats
        int tr = tid % TPR;
        int rg = tid / TPR;
        float4 s = make_float4(0.f, 0.f, 0.f, 0.f);
        float4 q = make_float4(0.f, 0.f, 0.f, 0.f);
        int stride = gridDim.x * RPB;
        #pragma unroll 4
        for (int r = blockIdx.x * RPB + rg; r < nrows; r += stride) {
            float4 v = __ldg((const float4*)(xin + (size_t)r * ld_in) + tr);
            s.x += v.x; s.y += v.y; s.z += v.z; s.w += v.w;
            q.x = fmaf(v.x, v.x, q.x); q.y = fmaf(v.y, v.y, q.y);
            q.z = fmaf(v.z, v.z, q.z); q.w = fmaf(v.w, v.w, q.w);
        }
        ((float4*)smS)[tid % 256] = s;   // tid in [0,256)
        ((float4*)smQ)[tid] = q;
        __syncthreads();
        if (rg == 0) {
            #pragma unroll
            for (int j = 1; j < RPB; j++) {
                float4 a = ((float4*)smS)[j * TPR + tr];
                float4 b = ((float4*)smQ)[j * TPR + tr];
                s.x += a.x; s.y += a.y; s.z += a.z; s.w += a.w;
                q.x += b.x; q.y += b.y; q.z += b.z; q.w += b.w;
            }
            int slot = blockIdx.x & (NSLOT - 1);
            int c = tr * 4;
            atomicAdd(&g_sums[slot][c + 0], (double)s.x);
            atomicAdd(&g_sums[slot][c + 1], (double)s.y);
            atomicAdd(&g_sums[slot][c + 2], (double)s.z);
            atomicAdd(&g_sums[slot][c + 3], (double)s.w);
            atomicAdd(&g_sums[slot][64 + c + 0], (double)q.x);
            atomicAdd(&g_sums[slot][64 + c + 1], (double)q.y);
            atomicAdd(&g_sums[slot][64 + c + 2], (double)q.z);
            atomicAdd(&g_sums[slot][64 + c + 3], (double)q.w);
            __threadfence();
        }
        __syncthreads();

        // ticket; my-gen read precedes this block's ticket -> no lost wakeup
        int my = 0;
        if (tid == 0) {
            my = *(volatile int*)&g_gen;
            lastsm = (atomicAdd(&g_stick, 1) == (int)gridDim.x - 1);
        }
        __syncthreads();

        if (lastsm) {                  // finalize scale/shift
            __threadfence();
            int c = tid;
            if (c < 64) {
                double ss = 0.0, s2 = 0.0;
                #pragma unroll
                for (int j = 0; j < NSLOT; j++) {
                    ss += g_sums[j][c];      g_sums[j][c] = 0.0;
                    s2 += g_sums[j][64 + c]; g_sums[j][64 + c] = 0.0;
                }
                if (c < CIN) {
                    float mu  = (float)(ss * inv_n);
                    float var = (float)(s2 * inv_n) - mu * mu;
                    float inv = rsqrtf(var + EPSF);
                    float sc  = gw[c] * inv;
                    g_scale[c] = sc;
                    g_shift[c] = bw[c] - mu * sc;
                }
            }
            __syncthreads();
            if (tid == 0) {
                g_stick = 0;
                __threadfence();
                atomicAdd(&g_gen, 1);  // release
            }
        }

        if (tid == 0) {                // spin until this stage's gen bump
            while (*(volatile int*)&g_gen == my) __nanosleep(64);
            __threadfence();           // acquire
        }
        __syncthreads();
    }

    // ---------------- phase B: tap-GEMM (R8 core) ----------------
    if (tid < CIN) { ssm[tid] = g_scale[tid]; bsm[tid] = g_shift[tid]; }
    if (tid <= K)  tbsm[tid] = tb[tid];
    if (tid <  K)  cntsm[tid] = cnt[tid];
    __syncthreads();

    int total = tbsm[K];
    int tx = tid % TX;
    int ty = tid / TX;
    int pa = ty * 4;

    for (int t = blockIdx.x; t < total; t += gridDim.x) {
        int k = 0;
        while (tbsm[k + 1] <= t) k++;
        int t0 = (t - tbsm[k]) * TP;
        int np = min(TP, cntsm[k] - t0);

        // stage W tap + pair chunk
        {
            const float4* Wg = (const float4*)(W + (size_t)k * CIN * COUT);
            for (int i = tid; i < CIN * COUT / 4; i += 256)
                ((float4*)Wsm)[i] = __ldg(&Wg[i]);
            if (tid < TP) {
                if (tid < np) {
                    int2 pr = __ldg(&pairs[(size_t)k * NMAX + t0 + tid]);
                    rowsm[tid] = pr.x; idxsm[tid] = pr.y;
                } else { rowsm[tid] = -1; idxsm[tid] = 0; }
            }
        }
        __syncthreads();

        // gather + BN + ReLU into padded Asm
        for (int i = tid; i < TP * C4; i += 256) {
            int p  = i / C4;
            int c4 = i % C4;
            float4 v = __ldg((const float4*)(xin + (size_t)idxsm[p] * ld_in) + c4);
            int c = c4 * 4;
            float* ap = &Asm[p * CP + c];
            ap[0] = fmaxf(fmaf(v.x, ssm[c + 0], bsm[c + 0]), 0.f);
            ap[1] = fmaxf(fmaf(v.y, ssm[c + 1], bsm[c + 1]), 0.f);
            ap[2] = fmaxf(fmaf(v.z, ssm[c + 2], bsm[c + 2]), 0.f);
            ap[3] = fmaxf(fmaf(v.w, ssm[c + 3], bsm[c + 3]), 0.f);
        }
        __syncthreads();

        // packed register-tiled GEMM
        unsigned long long acc[4][CU];
        #pragma unroll
        for (int i = 0; i < 4; i++)
            #pragma unroll
            for (int j = 0; j < CU; j++) acc[i][j] = 0ull;

        const float* a0p = &Asm[pa * CP];
        #pragma unroll 8
        for (int c = 0; c < CIN; c++) {
            unsigned long long aa0 = pack2(a0p[c]);
            unsigned long long aa1 = pack2(a0p[CP + c]);
            unsigned long long aa2 = pack2(a0p[2 * CP + c]);
            unsigned long long aa3 = pack2(a0p[3 * CP + c]);
            const ulonglong2* wr = (const ulonglong2*)&Wsm[c * COUT + tx * CT];
            ulonglong2 w2 = wr[0];
            fma2(acc[0][0], aa0, w2.x); fma2(acc[0][1], aa0, w2.y);
            fma2(acc[1][0], aa1, w2.x); fma2(acc[1][1], aa1, w2.y);
            fma2(acc[2][0], aa2, w2.x); fma2(acc[2][1], aa2, w2.y);
            fma2(acc[3][0], aa3, w2.x); fma2(acc[3][1], aa3, w2.y);
        }

        // write back
        #pragma unroll
        for (int i = 0; i < 4; i++) {
            int r = rowsm[pa + i];
            if (r >= 0) {
                float* op = out + (size_t)r * ld_out + tx * CT;
                U2F u0, u1; u0.u = acc[i][0]; u1.u = acc[i][1];
                if (DIRECT) {
                    *(float4*)op = make_float4(u0.f.x, u0.f.y, u1.f.x, u1.f.y);
                } else {
                    red_add_v4(op, u0.f.x, u0.f.y, u1.f.x, u1.f.y);
                }
            }
        }
        __syncthreads();
    }
}

// ---------------------------------------------------------------------------
extern "C" void kernel_launch(void* const* d_in, const int* in_sizes, int n_in,
                              void* d_out, int out_size) {
    const float* feat    = (const float*)d_in[0];
    const float* w_sub1  = (const float*)d_in[1];
    const float* w_down  = (const float*)d_in[2];
    const float* w_sub2  = (const float*)d_in[3];
    const float* w_up    = (const float*)d_in[4];
    const float* w_sub3  = (const float*)d_in[5];
    const float* g1 = (const float*)d_in[6];  const float* b1 = (const float*)d_in[7];
    const float* g2 = (const float*)d_in[8];  const float* b2 = (const float*)d_in[9];
    const float* g3 = (const float*)d_in[10]; const float* b3 = (const float*)d_in[11];
    const float* g4 = (const float*)d_in[12]; const float* b4 = (const float*)d_in[13];
    const float* g5 = (const float*)d_in[14]; const float* b5 = (const float*)d_in[15];
    const int* nbr_fine   = (const int*)d_in[16];
    const int* nbr_coarse = (const int*)d_in[17];
    const int* down_idx   = (const int*)d_in[18];
    const int* up_cidx    = (const int*)d_in[19];
    const int* up_k       = (const int*)d_in[20];

    const int N = in_sizes[0] / 32;
    const int M = in_sizes[18] / 8;

    float* buf;
    int *cnt_ptr, *tbf, *tbc, *tbd, *tbu;
    cudaGetSymbolAddress((void**)&buf, g_buf);
    cudaGetSymbolAddress((void**)&cnt_ptr, g_cnt);
    cudaGetSymbolAddress((void**)&tbf, g_tb_f);
    cudaGetSymbolAddress((void**)&tbc, g_tb_c);
    cudaGetSymbolAddress((void**)&tbd, g_tb_d);
    cudaGetSymbolAddress((void**)&tbu, g_tb_u);
    int2 *pf, *pc, *pd, *pu;
    cudaGetSymbolAddress((void**)&pf, g_pf);
    cudaGetSymbolAddress((void**)&pc, g_pc);
    cudaGetSymbolAddress((void**)&pd, g_pd);
    cudaGetSymbolAddress((void**)&pu, g_pu);

    float* cat_ptr = buf;
    float* xc_ptr  = buf + (size_t)NMAX * 64;
    float* xc2_ptr = buf + (size_t)NMAX * 64 * 2;

    // zero accumulation targets (cat/xc/xc2 contiguous -> one memset)
    cudaMemsetAsync(buf, 0, ((size_t)N * 64 +
                             (size_t)(NMAX + M) * 64) * sizeof(float));
    cudaMemsetAsync(d_out, 0, (size_t)out_size * sizeof(float));

    // geometry prep: counters, compaction + fused tile plan
    prep_kernel<<<1, 1024>>>();
    int mx = (N > M ? N : M);
    dim3 cg((mx + 2047) / 2048, 70);
    compact_all_kernel<<<cg, 256>>>(nbr_fine, nbr_coarse, down_idx, up_cidx, up_k, N, M);

    // stage 1: BN(feat) + subconv1 (32->32, fine taps) into cat[:,0:32]
    stage_kernel<32, 32, 128, 8, false><<<STAGE_GRID, 256>>>(
        feat, 32, N, g1, b1, 1.0f / N,
        pf, cnt_ptr + 0, tbf, 27, w_sub1, cat_ptr, 64);

    // stage 2: BN(skip) + down conv (32->64) into xc
    stage_kernel<32, 64, 64, 16, false><<<STAGE_GRID, 256>>>(
        cat_ptr, 64, N, g2, b2, 1.0f / N,
        pd, cnt_ptr + 54, tbd, 8, w_down, xc_ptr, 64);

    // stage 3: BN(xc) + subconv2 (64->64, coarse taps) into xc2
    stage_kernel<64, 64, 64, 16, false><<<STAGE_GRID, 256>>>(
        xc_ptr, 64, M, g3, b3, 1.0f / M,
        pc, cnt_ptr + 27, tbc, 27, w_sub2, xc2_ptr, 64);

    // stage 4: BN(xc2) + deconv (64->32) direct into cat[:,32:64]
    stage_kernel<64, 32, 128, 8, true><<<STAGE_GRID, 256>>>(
        xc2_ptr, 64, M, g4, b4, 1.0f / M,
        pu, cnt_ptr + 62, tbu, 8, w_up, cat_ptr + 32, 64);

    // stage 5: BN(cat) + subconv3 (64->32, fine taps) into out
    stage_kernel<64, 32, 128, 8, false><<<STAGE_GRID, 256>>>(
        cat_ptr, 64, N, g5, b5, 1.0f / N,
        pf, cnt_ptr + 0, tbf, 27, w_sub3, (float*)d_out, 32);
}